// round 2
// baseline (speedup 1.0000x reference)
#include <cuda_runtime.h>
#include <cuda_bf16.h>
#include <cstdint>
#include <cstddef>

#define Bn 16
#define Cn 64
#define Nn 2048
#define Kn 20
#define NBOT 6    // K - ceil(2K/3) = 20 - 14
#define TSEL 22   // fp32-preselected candidates per row

#define TM 128
#define TN 32

// ---- scratch (static device memory; no allocations allowed) ----
static __device__ float g_pd[(size_t)Bn * Nn * Nn];      // 268 MB pairwise "negative sq dist"
static __device__ float g_xx[Bn * Nn];                   // squared norms
static __device__ float g_xt[(size_t)Bn * Nn * Cn];     // transposed x, (B,N,C)
static __device__ int   g_cand[Bn * Nn * TSEL];          // fp32 top-22 candidates
static __device__ int   g_idx[Bn * Nn * Kn];             // exact top-K neighbor indices
static __device__ float g_x1t[(size_t)Bn * Cn * Nn];     // smoothed features, (B,C,N) layout

// ---------------- packed f32x2 helpers (Blackwell FFMA2 path) ----------------
__device__ __forceinline__ unsigned long long pack2(float lo, float hi) {
    unsigned long long r;
    asm("mov.b64 %0, {%1, %2};" : "=l"(r) : "f"(lo), "f"(hi));
    return r;
}
__device__ __forceinline__ void unpack2(unsigned long long v, float& lo, float& hi) {
    asm("mov.b64 {%0, %1}, %2;" : "=f"(lo), "=f"(hi) : "l"(v));
}
__device__ __forceinline__ unsigned long long fma2(unsigned long long a,
                                                   unsigned long long b,
                                                   unsigned long long c) {
    unsigned long long d;
    asm("fma.rn.f32x2 %0, %1, %2, %3;" : "=l"(d) : "l"(a), "l"(b), "l"(c));
    return d;
}

// ---------------- K0: transpose x (B,C,N) -> g_xt (B,N,C) ----------------
__global__ __launch_bounds__(256) void xt_kernel(const float* __restrict__ x) {
    __shared__ float tile[32][33];
    int b = blockIdx.z, c0 = blockIdx.y * 32, n0 = blockIdx.x * 32;
    int tx = threadIdx.x & 31, ty = threadIdx.x >> 5;   // 32 x 8
#pragma unroll
    for (int i = ty; i < 32; i += 8)
        tile[i][tx] = x[((size_t)(b * Cn + c0 + i) << 11) + n0 + tx];
    __syncthreads();
#pragma unroll
    for (int i = ty; i < 32; i += 8)
        g_xt[(size_t)((b << 11) + n0 + i) * Cn + c0 + tx] = tile[tx][i];
}

// ---------------- K1: squared norms ----------------
__global__ void xx_kernel(const float* __restrict__ x) {
    int t = blockIdx.x * blockDim.x + threadIdx.x;
    if (t >= Bn * Nn) return;
    int b = t >> 11, n = t & (Nn - 1);
    const float* xp = x + (size_t)b * Cn * Nn + n;
    float s = 0.f;
#pragma unroll
    for (int c = 0; c < Cn; c++) {
        float v = xp[(size_t)c * Nn];
        s = fmaf(v, v, s);
    }
    g_xx[t] = s;
}

// ---------------- K2: pd = 2*X^T X - xx_n - xx_m ----------------
__global__ __launch_bounds__(256) void pd_gemm_kernel(const float* __restrict__ x) {
    __shared__ float sA[Cn][TN];   // [c][n]  8 KB
    __shared__ float sB[Cn][TM];   // [c][m] 32 KB
    int b  = blockIdx.z;
    int n0 = blockIdx.y * TN;
    int m0 = blockIdx.x * TM;
    int t  = threadIdx.x;
    const float* xb = x + (size_t)b * Cn * Nn;

#pragma unroll
    for (int p = 0; p < 2; p++) {
        int lin = t + p * 256;
        int c = lin >> 3, i4 = lin & 7;
        *(float4*)&sA[c][i4 * 4] = *(const float4*)(xb + (size_t)c * Nn + n0 + i4 * 4);
    }
#pragma unroll
    for (int p = 0; p < 8; p++) {
        int lin = t + p * 256;
        int c = lin >> 5, i4 = lin & 31;
        *(float4*)&sB[c][i4 * 4] = *(const float4*)(xb + (size_t)c * Nn + m0 + i4 * 4);
    }
    __syncthreads();

    int tx = t & 15, ty = t >> 4;
    unsigned long long acc[2][4] = {};

#pragma unroll 16
    for (int c = 0; c < Cn; c++) {
        float2 a2 = *(const float2*)&sA[c][ty * 2];
        unsigned long long a0 = pack2(a2.x, a2.x);
        unsigned long long a1 = pack2(a2.y, a2.y);
        const ulonglong2* bp = (const ulonglong2*)&sB[c][tx * 8];
        ulonglong2 B0 = bp[0];
        ulonglong2 B1 = bp[1];
        acc[0][0] = fma2(B0.x, a0, acc[0][0]);
        acc[0][1] = fma2(B0.y, a0, acc[0][1]);
        acc[0][2] = fma2(B1.x, a0, acc[0][2]);
        acc[0][3] = fma2(B1.y, a0, acc[0][3]);
        acc[1][0] = fma2(B0.x, a1, acc[1][0]);
        acc[1][1] = fma2(B0.y, a1, acc[1][1]);
        acc[1][2] = fma2(B1.x, a1, acc[1][2]);
        acc[1][3] = fma2(B1.y, a1, acc[1][3]);
    }

    int mbase = m0 + tx * 8;
    float xxm[8];
#pragma unroll
    for (int q = 0; q < 8; q++) xxm[q] = g_xx[b * Nn + mbase + q];

#pragma unroll
    for (int r = 0; r < 2; r++) {
        int n = n0 + ty * 2 + r;
        float xxn = g_xx[b * Nn + n];
        float o[8];
#pragma unroll
        for (int q = 0; q < 4; q++) {
            float d0, d1;
            unpack2(acc[r][q], d0, d1);
            o[q * 2]     = 2.f * d0 - xxn - xxm[q * 2];
            o[q * 2 + 1] = 2.f * d1 - xxn - xxm[q * 2 + 1];
        }
        float* op = g_pd + (size_t)b * Nn * Nn + (size_t)n * Nn + mbase;
        *(float4*)op       = make_float4(o[0], o[1], o[2], o[3]);
        *(float4*)(op + 4) = make_float4(o[4], o[5], o[6], o[7]);
    }
}

// ---------------- K3: warp-per-row fp32 top-22 preselect ----------------
__global__ __launch_bounds__(256) void topk_kernel() {
    const unsigned FULL = 0xffffffffu;
    int row  = (blockIdx.x << 3) + (threadIdx.x >> 5);   // b*N + n
    int lane = threadIdx.x & 31;

    const float4* rp = (const float4*)(g_pd + (size_t)row * Nn);

    float bval = -INFINITY;   // distributed sorted list: lane j holds slot j
    int   bidx = 0;
    float thr  = -INFINITY;   // current slot-(TSEL-1) value

    for (int tc = 0; tc < 16; tc++) {
        float4 v = rp[tc * 32 + lane];
        float lmax = fmaxf(fmaxf(v.x, v.y), fmaxf(v.z, v.w));
        unsigned act = __ballot_sync(FULL, lmax > thr);
        while (act) {
            int s = __ffs((int)act) - 1;
            act &= act - 1;
            float c0 = __shfl_sync(FULL, v.x, s);
            float c1 = __shfl_sync(FULL, v.y, s);
            float c2 = __shfl_sync(FULL, v.z, s);
            float c3 = __shfl_sync(FULL, v.w, s);
            int mb = tc * 128 + s * 4;
            float cs[4] = {c0, c1, c2, c3};
#pragma unroll
            for (int i = 0; i < 4; i++) {
                float cv = cs[i];               // uniform across warp
                if (cv > thr) {                 // uniform branch
                    unsigned lt = __ballot_sync(FULL, bval < cv);
                    int pos = __ffs((int)lt) - 1;
                    float upv = __shfl_up_sync(FULL, bval, 1);
                    int   upi = __shfl_up_sync(FULL, bidx, 1);
                    if (lane > pos)      { bval = upv; bidx = upi; }
                    else if (lane == pos){ bval = cv;  bidx = mb + i; }
                    thr = __shfl_sync(FULL, bval, TSEL - 1);
                }
            }
        }
    }

    if (lane < TSEL) g_cand[row * TSEL + lane] = bidx;
}

// ---------------- K3b: exact fp64 re-ranking of the 22 candidates ----------------
__global__ __launch_bounds__(256) void refine_kernel(float* __restrict__ out, int write_idx) {
    __shared__ float sxn[8][Cn];
    const unsigned FULL = 0xffffffffu;
    int warp = threadIdx.x >> 5, lane = threadIdx.x & 31;
    int row = (blockIdx.x << 3) + warp;
    int b = row >> 11;

    const float* xn = g_xt + (size_t)row * Cn;
    sxn[warp][lane]      = xn[lane];
    sxn[warp][lane + 32] = xn[lane + 32];
    __syncwarp();

    double sv = -1.0e300;
    int m = 0x7fffffff;
    if (lane < TSEL) {
        m = g_cand[row * TSEL + lane];
        const float4* xm4 = (const float4*)(g_xt + (size_t)((b << 11) + m) * Cn);
        double dot = 0.0, xx = 0.0;
#pragma unroll
        for (int q = 0; q < 16; q++) {
            float4 v = xm4[q];
            double v0 = v.x, v1 = v.y, v2 = v.z, v3 = v.w;
            dot += (double)sxn[warp][q * 4]     * v0;
            dot += (double)sxn[warp][q * 4 + 1] * v1;
            dot += (double)sxn[warp][q * 4 + 2] * v2;
            dot += (double)sxn[warp][q * 4 + 3] * v3;
            xx  += v0 * v0 + v1 * v1 + v2 * v2 + v3 * v3;
        }
        sv = 2.0 * dot - xx;     // exact ranking score (shift by +xx_n is rank-invariant)
    }

    // stable O(TSEL^2) rank: ties -> lower point index first (matches lax.top_k)
    int rank = 0;
#pragma unroll
    for (int i = 0; i < TSEL; i++) {
        double vi = __shfl_sync(FULL, sv, i);
        int    mi = __shfl_sync(FULL, m, i);
        if (i != lane && (vi > sv || (vi == sv && mi < m))) rank++;
    }
    if (lane < TSEL && rank < Kn) {
        g_idx[row * Kn + rank] = m;
        if (write_idx) {
            const size_t FEAT = (size_t)Bn * 2 * Cn * Nn * Kn;   // 83886080
            out[FEAT + (size_t)row * Kn + rank] = (float)(m + b * Nn);
        }
    }
}

// ---------------- K4: x1t[b][c][n] = mean of top-14 of 20 gathered values ----------------
__global__ __launch_bounds__(256) void smooth_kernel(const float* __restrict__ x) {
    int t = blockIdx.x * 256 + threadIdx.x;            // over B*C*N = 2097152
    int n = t & (Nn - 1);
    int c = (t >> 11) & (Cn - 1);
    int b = t >> 17;
    const int* ip = g_idx + ((b << 11) + n) * Kn;
    const float* xr = x + ((size_t)(b * Cn + c) << 11);

    float s = 0.f;
    float bot[NBOT];
#pragma unroll
    for (int q = 0; q < NBOT; q++) bot[q] = INFINITY;  // ascending min-list

#pragma unroll
    for (int j = 0; j < Kn; j++) {
        float v = xr[ip[j]];
        s += v;
        if (v < bot[NBOT - 1]) {
            bot[NBOT - 1] = v;
#pragma unroll
            for (int q = NBOT - 1; q > 0; q--) {
                float a = bot[q - 1], bb = bot[q];
                bot[q - 1] = fminf(a, bb);
                bot[q]     = fmaxf(a, bb);
            }
        }
    }
    float bs = bot[0] + bot[1] + bot[2] + bot[3] + bot[4] + bot[5];
    g_x1t[((size_t)(b * Cn + c) << 11) + n] = (s - bs) * (1.0f / 14.0f);
}

// ---------------- K5: feature (B, 2C, N, K) ----------------
__global__ __launch_bounds__(256) void feature_kernel(const float* __restrict__ x,
                                                      float* __restrict__ out) {
    unsigned f = blockIdx.x * 256u + threadIdx.x;      // < 83886080 (< 2^27)
    unsigned j = f % 20u;
    unsigned r = f / 20u;
    unsigned n = r & (Nn - 1);
    unsigned r2 = r >> 11;
    unsigned ch = r2 & 127u;
    unsigned b = r2 >> 7;

    float val;
    if (ch >= (unsigned)Cn) {
        val = x[((size_t)(b * Cn + (ch - Cn)) << 11) + n];
    } else {
        int m = g_idx[((b << 11) + n) * Kn + j];
        size_t rowo = (size_t)(b * Cn + ch) << 11;
        val = g_x1t[rowo + m] - x[rowo + n];
    }
    out[f] = val;
}

// ---------------- launch ----------------
extern "C" void kernel_launch(void* const* d_in, const int* in_sizes, int n_in,
                              void* d_out, int out_size) {
    const float* x = nullptr;
    for (int i = 0; i < n_in; i++) {
        if (in_sizes[i] == Bn * Cn * Nn) { x = (const float*)d_in[i]; break; }
    }
    float* out = (float*)d_out;

    const long long FEAT = (long long)Bn * 2 * Cn * Nn * Kn;          // 83886080
    const long long IDXE = (long long)Bn * Nn * Kn;                   // 655360
    int write_idx = ((long long)out_size >= FEAT + IDXE) ? 1 : 0;

    dim3 gt(Nn / 32, Cn / 32, Bn);
    xt_kernel<<<gt, 256>>>(x);

    xx_kernel<<<(Bn * Nn + 255) / 256, 256>>>(x);

    dim3 g2(Nn / TM, Nn / TN, Bn);                                    // (16, 64, 16)
    pd_gemm_kernel<<<g2, 256>>>(x);

    topk_kernel<<<Bn * Nn / 8, 256>>>();                              // 4096 blocks

    refine_kernel<<<Bn * Nn / 8, 256>>>(out, write_idx);              // 4096 blocks

    smooth_kernel<<<Bn * Cn * Nn / 256, 256>>>(x);                    // 8192 blocks

    feature_kernel<<<(unsigned)(FEAT / 256), 256>>>(x, out);          // 327680 blocks
}

// round 3
// speedup vs baseline: 1.1182x; 1.1182x over previous
#include <cuda_runtime.h>
#include <cuda_bf16.h>
#include <cstdint>
#include <cstddef>

#define Bn 16
#define Cn 64
#define Nn 2048
#define Kn 20
#define NBOT 6    // K - ceil(2K/3)
#define TSEL 22   // preselected candidates per row

// ---- scratch (static device memory; no allocations allowed) ----
static __device__ float g_xx[Bn * Nn];                   // squared norms
static __device__ float g_xt[(size_t)Bn * Nn * Cn];      // transposed x, (B,N,C)
static __device__ int   g_cand[Bn * Nn * TSEL];          // fp32 top-22 candidates
static __device__ int   g_idx[Bn * Nn * Kn];             // exact top-K neighbor indices
static __device__ float g_x1t[(size_t)Bn * Cn * Nn];     // smoothed features, (B,C,N)

// ---------------- packed f32x2 helpers ----------------
__device__ __forceinline__ unsigned long long pack2(float lo, float hi) {
    unsigned long long r;
    asm("mov.b64 %0, {%1, %2};" : "=l"(r) : "f"(lo), "f"(hi));
    return r;
}
__device__ __forceinline__ void unpack2(unsigned long long v, float& lo, float& hi) {
    asm("mov.b64 {%0, %1}, %2;" : "=f"(lo), "=f"(hi) : "l"(v));
}
__device__ __forceinline__ unsigned long long fma2(unsigned long long a,
                                                   unsigned long long b,
                                                   unsigned long long c) {
    unsigned long long d;
    asm("fma.rn.f32x2 %0, %1, %2, %3;" : "=l"(d) : "l"(a), "l"(b), "l"(c));
    return d;
}

// ---------------- K0: transpose x (B,C,N) -> g_xt (B,N,C) ----------------
__global__ __launch_bounds__(256) void xt_kernel(const float* __restrict__ x) {
    __shared__ float tile[32][33];
    int b = blockIdx.z, c0 = blockIdx.y * 32, n0 = blockIdx.x * 32;
    int tx = threadIdx.x & 31, ty = threadIdx.x >> 5;
#pragma unroll
    for (int i = ty; i < 32; i += 8)
        tile[i][tx] = x[((size_t)(b * Cn + c0 + i) << 11) + n0 + tx];
    __syncthreads();
#pragma unroll
    for (int i = ty; i < 32; i += 8)
        g_xt[(size_t)((b << 11) + n0 + i) * Cn + c0 + tx] = tile[tx][i];
}

// ---------------- K1: squared norms ----------------
__global__ void xx_kernel(const float* __restrict__ x) {
    int t = blockIdx.x * blockDim.x + threadIdx.x;
    if (t >= Bn * Nn) return;
    int b = t >> 11, n = t & (Nn - 1);
    const float* xp = x + (size_t)b * Cn * Nn + n;
    float s = 0.f;
#pragma unroll
    for (int c = 0; c < Cn; c++) {
        float v = xp[(size_t)c * Nn];
        s = fmaf(v, v, s);
    }
    g_xx[t] = s;
}

// ---------------- K2: fused pd-GEMM + top-22 preselect ----------------
// Block: 128 n-rows (blockIdx.x tile) x one batch (blockIdx.y), loops over all
// 16 m-tiles of 128. 256 threads, 8x8 micro-tile, f32x2 FMAs. Scores staged to
// smem in 32-row quarters; 8 warps run a ballot-threshold filter maintaining
// per-row sorted top-22 lists (score = 2*dot - ||x_m||^2; -||x_n||^2 dropped,
// rank-invariant).
//
// smem layout (bytes):
//   sA   [64][128] f32      0 .. 32768
//   sB   [64][128] f32  32768 .. 65536
//   sP   [32][128] f32  65536 .. 81920
//   sXX  [128]     f32  81920 .. 82432
//   sVal [128][22] f32  82432 .. 93696
//   sIdx [128][22] i32  93696 .. 104960
#define SM_TOTAL 104960

__global__ __launch_bounds__(256, 2) void knn_kernel(const float* __restrict__ x) {
    extern __shared__ char sm[];
    float (*sA)[128]   = (float(*)[128])(sm);
    float (*sB)[128]   = (float(*)[128])(sm + 32768);
    float (*sP)[128]   = (float(*)[128])(sm + 65536);
    float* sXX         = (float*)(sm + 81920);
    float (*sVal)[TSEL] = (float(*)[TSEL])(sm + 82432);
    int   (*sIdx)[TSEL] = (int(*)[TSEL])(sm + 93696);

    const unsigned FULL = 0xffffffffu;
    int t    = threadIdx.x;
    int lane = t & 31;
    int w    = t >> 5;
    int tx   = t & 15;           // m micro-group
    int ty   = t >> 4;           // n micro-group
    int b    = blockIdx.y;
    int n0   = blockIdx.x * 128;
    const float* xb = x + (size_t)b * Cn * Nn;

    // init candidate lists
    for (int i = t; i < 128 * TSEL; i += 256) {
        ((float*)sVal)[i] = -INFINITY;
        ((int*)sIdx)[i]   = 0;
    }
    // load A tile (128 n x 64 c), stored [c][n]
#pragma unroll
    for (int p = 0; p < 8; p++) {
        int lin = t + p * 256;
        int c = lin >> 5, i4 = lin & 31;
        *(float4*)&sA[c][i4 * 4] = *(const float4*)(xb + (size_t)c * Nn + n0 + i4 * 4);
    }

    for (int mt = 0; mt < 16; mt++) {
        int m0 = mt * 128;
        __syncthreads();   // previous iter's q3 filter + c-loop reads of sB done
        // load B tile (128 m x 64 c), stored [c][m]
#pragma unroll
        for (int p = 0; p < 8; p++) {
            int lin = t + p * 256;
            int c = lin >> 5, i4 = lin & 31;
            *(float4*)&sB[c][i4 * 4] = *(const float4*)(xb + (size_t)c * Nn + m0 + i4 * 4);
        }
        if (t < 32) *(float4*)&sXX[t * 4] = *(const float4*)(g_xx + b * Nn + m0 + t * 4);
        __syncthreads();

        // ---- compute 128x128 tile: micro 8x8 per thread ----
        // rows: {ty*4+i} u {64+ty*4+i}; cols: {tx*4+j} u {64+tx*4+j}
        unsigned long long acc[2][4][4];
#pragma unroll
        for (int h = 0; h < 2; h++)
#pragma unroll
            for (int i = 0; i < 4; i++)
#pragma unroll
                for (int p = 0; p < 4; p++) acc[h][i][p] = 0ull;

#pragma unroll 8
        for (int c = 0; c < Cn; c++) {
            float4 aLo = *(float4*)&sA[c][ty * 4];
            float4 aHi = *(float4*)&sA[c][64 + ty * 4];
            ulonglong2 b0 = *(ulonglong2*)&sB[c][tx * 4];
            ulonglong2 b1 = *(ulonglong2*)&sB[c][64 + tx * 4];
            const float* al = &aLo.x;
            const float* ah = &aHi.x;
#pragma unroll
            for (int i = 0; i < 4; i++) {
                unsigned long long a0 = pack2(al[i], al[i]);
                acc[0][i][0] = fma2(b0.x, a0, acc[0][i][0]);
                acc[0][i][1] = fma2(b0.y, a0, acc[0][i][1]);
                acc[0][i][2] = fma2(b1.x, a0, acc[0][i][2]);
                acc[0][i][3] = fma2(b1.y, a0, acc[0][i][3]);
                unsigned long long a1 = pack2(ah[i], ah[i]);
                acc[1][i][0] = fma2(b0.x, a1, acc[1][i][0]);
                acc[1][i][1] = fma2(b0.y, a1, acc[1][i][1]);
                acc[1][i][2] = fma2(b1.x, a1, acc[1][i][2]);
                acc[1][i][3] = fma2(b1.y, a1, acc[1][i][3]);
            }
        }

        float4 xxLo = *(float4*)&sXX[tx * 4];
        float4 xxHi = *(float4*)&sXX[64 + tx * 4];

        // ---- stage + filter in 32-row quarters ----
#pragma unroll
        for (int q = 0; q < 4; q++) {
            __syncthreads();   // previous quarter's filter done reading sP
            int nh = q >> 1;
            if (((ty >> 3) & 1) == (q & 1)) {
                int rl = (ty & 7) * 4;
#pragma unroll
                for (int i = 0; i < 4; i++) {
                    float s0, s1, s2, s3, s4, s5, s6, s7;
                    unpack2(acc[nh][i][0], s0, s1);
                    unpack2(acc[nh][i][1], s2, s3);
                    unpack2(acc[nh][i][2], s4, s5);
                    unpack2(acc[nh][i][3], s6, s7);
                    *(float4*)&sP[rl + i][tx * 4] = make_float4(
                        2.f * s0 - xxLo.x, 2.f * s1 - xxLo.y,
                        2.f * s2 - xxLo.z, 2.f * s3 - xxLo.w);
                    *(float4*)&sP[rl + i][64 + tx * 4] = make_float4(
                        2.f * s4 - xxHi.x, 2.f * s5 - xxHi.y,
                        2.f * s6 - xxHi.z, 2.f * s7 - xxHi.w);
                }
            }
            __syncthreads();

            // 8 warps x 4 rows each
#pragma unroll
            for (int rr = 0; rr < 4; rr++) {
                int rl = w * 4 + rr;          // local row in sP
                int gr = q * 32 + rl;         // block-local row (0..127)
                float lv = -INFINITY; int li = 0;
                if (lane < TSEL) { lv = sVal[gr][lane]; li = sIdx[gr][lane]; }
                float thr = __shfl_sync(FULL, lv, TSEL - 1);
                float4 v = *(float4*)&sP[rl][lane * 4];
                float lmax = fmaxf(fmaxf(v.x, v.y), fmaxf(v.z, v.w));
                unsigned act = __ballot_sync(FULL, lmax > thr);
                while (act) {
                    int s = __ffs((int)act) - 1;
                    act &= act - 1;
                    float c0 = __shfl_sync(FULL, v.x, s);
                    float c1 = __shfl_sync(FULL, v.y, s);
                    float c2 = __shfl_sync(FULL, v.z, s);
                    float c3 = __shfl_sync(FULL, v.w, s);
                    int mb = m0 + s * 4;
                    float cs[4] = {c0, c1, c2, c3};
#pragma unroll
                    for (int i = 0; i < 4; i++) {
                        float cv = cs[i];
                        if (cv > thr) {            // warp-uniform
                            unsigned lt = __ballot_sync(FULL, lv < cv);
                            int pos = __ffs((int)lt) - 1;
                            float upv = __shfl_up_sync(FULL, lv, 1);
                            int   upi = __shfl_up_sync(FULL, li, 1);
                            if (lane > pos)       { lv = upv; li = upi; }
                            else if (lane == pos) { lv = cv;  li = mb + i; }
                            thr = __shfl_sync(FULL, lv, TSEL - 1);
                        }
                    }
                }
                if (lane < TSEL) { sVal[gr][lane] = lv; sIdx[gr][lane] = li; }
            }
        }
    }
    __syncthreads();

    // write candidate lists
    int rowbase = (b << 11) + n0;
#pragma unroll
    for (int rr = 0; rr < 16; rr++) {
        int gr = w * 16 + rr;
        if (lane < TSEL) g_cand[(rowbase + gr) * TSEL + lane] = sIdx[gr][lane];
    }
}

// ---------------- K3: exact fp64 re-ranking of the 22 candidates ----------------
__global__ __launch_bounds__(256) void refine_kernel(float* __restrict__ out, int write_idx) {
    __shared__ float sxn[8][Cn];
    const unsigned FULL = 0xffffffffu;
    int warp = threadIdx.x >> 5, lane = threadIdx.x & 31;
    int row = (blockIdx.x << 3) + warp;
    int b = row >> 11;

    const float* xn = g_xt + (size_t)row * Cn;
    sxn[warp][lane]      = xn[lane];
    sxn[warp][lane + 32] = xn[lane + 32];
    __syncwarp();

    double sv = -1.0e300;
    int m = 0x7fffffff;
    if (lane < TSEL) {
        m = g_cand[row * TSEL + lane];
        const float4* xm4 = (const float4*)(g_xt + (size_t)((b << 11) + m) * Cn);
        double dot = 0.0, xx = 0.0;
#pragma unroll
        for (int q = 0; q < 16; q++) {
            float4 v = xm4[q];
            double v0 = v.x, v1 = v.y, v2 = v.z, v3 = v.w;
            dot += (double)sxn[warp][q * 4]     * v0;
            dot += (double)sxn[warp][q * 4 + 1] * v1;
            dot += (double)sxn[warp][q * 4 + 2] * v2;
            dot += (double)sxn[warp][q * 4 + 3] * v3;
            xx  += v0 * v0 + v1 * v1 + v2 * v2 + v3 * v3;
        }
        sv = 2.0 * dot - xx;
    }

    int rank = 0;
#pragma unroll
    for (int i = 0; i < TSEL; i++) {
        double vi = __shfl_sync(FULL, sv, i);
        int    mi = __shfl_sync(FULL, m, i);
        if (i != lane && (vi > sv || (vi == sv && mi < m))) rank++;
    }
    if (lane < TSEL && rank < Kn) {
        g_idx[row * Kn + rank] = m;
        if (write_idx) {
            const size_t FEAT = (size_t)Bn * 2 * Cn * Nn * Kn;
            out[FEAT + (size_t)row * Kn + rank] = (float)(m + b * Nn);
        }
    }
}

// ---------------- K4: branchless top-14-of-20 mean ----------------
__global__ __launch_bounds__(256) void smooth_kernel(const float* __restrict__ x) {
    int t = blockIdx.x * 256 + threadIdx.x;
    int n = t & (Nn - 1);
    int c = (t >> 11) & (Cn - 1);
    int b = t >> 17;
    const int* ip = g_idx + ((b << 11) + n) * Kn;
    const float* xr = x + ((size_t)(b * Cn + c) << 11);

    float s = 0.f;
    float bot[NBOT];
#pragma unroll
    for (int q = 0; q < NBOT; q++) bot[q] = INFINITY;

#pragma unroll
    for (int j = 0; j < Kn; j++) {
        float v = xr[ip[j]];
        s += v;
        float nv = v;
#pragma unroll
        for (int q = 0; q < NBOT; q++) {          // branchless ascending insert
            float lo = fminf(bot[q], nv);
            float hi = fmaxf(bot[q], nv);
            bot[q] = lo; nv = hi;
        }
    }
    float bs = bot[0] + bot[1] + bot[2] + bot[3] + bot[4] + bot[5];
    g_x1t[((size_t)(b * Cn + c) << 11) + n] = (s - bs) * (1.0f / 14.0f);
}

// ---------------- K5: feature (B, 2C, N, K) ----------------
__global__ __launch_bounds__(256) void feature_kernel(const float* __restrict__ x,
                                                      float* __restrict__ out) {
    unsigned f = blockIdx.x * 256u + threadIdx.x;
    unsigned j = f % 20u;
    unsigned r = f / 20u;
    unsigned n = r & (Nn - 1);
    unsigned r2 = r >> 11;
    unsigned ch = r2 & 127u;
    unsigned b = r2 >> 7;

    float val;
    if (ch >= (unsigned)Cn) {
        val = x[((size_t)(b * Cn + (ch - Cn)) << 11) + n];
    } else {
        int m = g_idx[((b << 11) + n) * Kn + j];
        size_t rowo = (size_t)(b * Cn + ch) << 11;
        val = g_x1t[rowo + m] - x[rowo + n];
    }
    out[f] = val;
}

// ---------------- launch ----------------
extern "C" void kernel_launch(void* const* d_in, const int* in_sizes, int n_in,
                              void* d_out, int out_size) {
    const float* x = nullptr;
    for (int i = 0; i < n_in; i++) {
        if (in_sizes[i] == Bn * Cn * Nn) { x = (const float*)d_in[i]; break; }
    }
    float* out = (float*)d_out;

    const long long FEAT = (long long)Bn * 2 * Cn * Nn * Kn;          // 83886080
    const long long IDXE = (long long)Bn * Nn * Kn;                   // 655360
    int write_idx = ((long long)out_size >= FEAT + IDXE) ? 1 : 0;

    cudaFuncSetAttribute(knn_kernel, cudaFuncAttributeMaxDynamicSharedMemorySize, SM_TOTAL);

    dim3 gt(Nn / 32, Cn / 32, Bn);
    xt_kernel<<<gt, 256>>>(x);

    xx_kernel<<<(Bn * Nn + 255) / 256, 256>>>(x);

    dim3 gk(Nn / 128, Bn);                                            // (16, 16)
    knn_kernel<<<gk, 256, SM_TOTAL>>>(x);

    refine_kernel<<<Bn * Nn / 8, 256>>>(out, write_idx);

    smooth_kernel<<<Bn * Cn * Nn / 256, 256>>>(x);

    feature_kernel<<<(unsigned)(FEAT / 256), 256>>>(x, out);
}

// round 6
// speedup vs baseline: 1.8340x; 1.6402x over previous
#include <cuda_runtime.h>
#include <cuda_bf16.h>
#include <cstdint>
#include <cstddef>

#define Bn 16
#define Cn 64
#define Nn 2048
#define Kn 20
#define NBOT 6    // K - ceil(2K/3)
#define TSEL 22   // preselected candidates per row

// ---- scratch (static device memory; no allocations allowed) ----
static __device__ float g_xx[Bn * Nn];                   // squared norms
static __device__ float g_xt[(size_t)Bn * Nn * Cn];      // transposed x, (B,N,C)
static __device__ int   g_cand[Bn * Nn * TSEL];          // fp32 top-22 candidates
static __device__ int   g_idx[Bn * Nn * Kn];             // exact top-K neighbor indices
static __device__ float g_x1t[(size_t)Bn * Cn * Nn];     // smoothed features, (B,C,N)

// ---------------- packed f32x2 helpers ----------------
__device__ __forceinline__ unsigned long long pack2(float lo, float hi) {
    unsigned long long r;
    asm("mov.b64 %0, {%1, %2};" : "=l"(r) : "f"(lo), "f"(hi));
    return r;
}
__device__ __forceinline__ void unpack2(unsigned long long v, float& lo, float& hi) {
    asm("mov.b64 {%0, %1}, %2;" : "=f"(lo), "=f"(hi) : "l"(v));
}
__device__ __forceinline__ unsigned long long fma2(unsigned long long a,
                                                   unsigned long long b,
                                                   unsigned long long c) {
    unsigned long long d;
    asm("fma.rn.f32x2 %0, %1, %2, %3;" : "=l"(d) : "l"(a), "l"(b), "l"(c));
    return d;
}

// ---------------- K0: transpose x (B,C,N) -> g_xt (B,N,C) ----------------
__global__ __launch_bounds__(256) void xt_kernel(const float* __restrict__ x) {
    __shared__ float tile[32][33];
    int b = blockIdx.z, c0 = blockIdx.y * 32, n0 = blockIdx.x * 32;
    int tx = threadIdx.x & 31, ty = threadIdx.x >> 5;
#pragma unroll
    for (int i = ty; i < 32; i += 8)
        tile[i][tx] = x[((size_t)(b * Cn + c0 + i) << 11) + n0 + tx];
    __syncthreads();
#pragma unroll
    for (int i = ty; i < 32; i += 8)
        g_xt[(size_t)((b << 11) + n0 + i) * Cn + c0 + tx] = tile[tx][i];
}

// ---------------- K1: squared norms ----------------
__global__ void xx_kernel(const float* __restrict__ x) {
    int t = blockIdx.x * blockDim.x + threadIdx.x;
    if (t >= Bn * Nn) return;
    int b = t >> 11, n = t & (Nn - 1);
    const float* xp = x + (size_t)b * Cn * Nn + n;
    float s = 0.f;
#pragma unroll
    for (int c = 0; c < Cn; c++) {
        float v = xp[(size_t)c * Nn];
        s = fmaf(v, v, s);
    }
    g_xx[t] = s;
}

// ---------------- K2: fused pd-GEMM + top-22 preselect ----------------
#define SM_TOTAL 104960

__global__ __launch_bounds__(256, 2) void knn_kernel(const float* __restrict__ x) {
    extern __shared__ char sm[];
    float (*sA)[128]   = (float(*)[128])(sm);
    float (*sB)[128]   = (float(*)[128])(sm + 32768);
    float (*sP)[128]   = (float(*)[128])(sm + 65536);
    float* sXX         = (float*)(sm + 81920);
    float (*sVal)[TSEL] = (float(*)[TSEL])(sm + 82432);
    int   (*sIdx)[TSEL] = (int(*)[TSEL])(sm + 93696);

    const unsigned FULL = 0xffffffffu;
    int t    = threadIdx.x;
    int lane = t & 31;
    int w    = t >> 5;
    int tx   = t & 15;           // m micro-group
    int ty   = t >> 4;           // n micro-group
    int b    = blockIdx.y;
    int n0   = blockIdx.x * 128;
    const float* xb = x + (size_t)b * Cn * Nn;

    for (int i = t; i < 128 * TSEL; i += 256) {
        ((float*)sVal)[i] = -INFINITY;
        ((int*)sIdx)[i]   = 0;
    }
#pragma unroll
    for (int p = 0; p < 8; p++) {
        int lin = t + p * 256;
        int c = lin >> 5, i4 = lin & 31;
        *(float4*)&sA[c][i4 * 4] = *(const float4*)(xb + (size_t)c * Nn + n0 + i4 * 4);
    }

    for (int mt = 0; mt < 16; mt++) {
        int m0 = mt * 128;
        __syncthreads();
#pragma unroll
        for (int p = 0; p < 8; p++) {
            int lin = t + p * 256;
            int c = lin >> 5, i4 = lin & 31;
            *(float4*)&sB[c][i4 * 4] = *(const float4*)(xb + (size_t)c * Nn + m0 + i4 * 4);
        }
        if (t < 32) *(float4*)&sXX[t * 4] = *(const float4*)(g_xx + b * Nn + m0 + t * 4);
        __syncthreads();

        unsigned long long acc[2][4][4];
#pragma unroll
        for (int h = 0; h < 2; h++)
#pragma unroll
            for (int i = 0; i < 4; i++)
#pragma unroll
                for (int p = 0; p < 4; p++) acc[h][i][p] = 0ull;

#pragma unroll 8
        for (int c = 0; c < Cn; c++) {
            float4 aLo = *(float4*)&sA[c][ty * 4];
            float4 aHi = *(float4*)&sA[c][64 + ty * 4];
            ulonglong2 b0 = *(ulonglong2*)&sB[c][tx * 4];
            ulonglong2 b1 = *(ulonglong2*)&sB[c][64 + tx * 4];
            const float* al = &aLo.x;
            const float* ah = &aHi.x;
#pragma unroll
            for (int i = 0; i < 4; i++) {
                unsigned long long a0 = pack2(al[i], al[i]);
                acc[0][i][0] = fma2(b0.x, a0, acc[0][i][0]);
                acc[0][i][1] = fma2(b0.y, a0, acc[0][i][1]);
                acc[0][i][2] = fma2(b1.x, a0, acc[0][i][2]);
                acc[0][i][3] = fma2(b1.y, a0, acc[0][i][3]);
                unsigned long long a1 = pack2(ah[i], ah[i]);
                acc[1][i][0] = fma2(b0.x, a1, acc[1][i][0]);
                acc[1][i][1] = fma2(b0.y, a1, acc[1][i][1]);
                acc[1][i][2] = fma2(b1.x, a1, acc[1][i][2]);
                acc[1][i][3] = fma2(b1.y, a1, acc[1][i][3]);
            }
        }

        float4 xxLo = *(float4*)&sXX[tx * 4];
        float4 xxHi = *(float4*)&sXX[64 + tx * 4];

#pragma unroll
        for (int q = 0; q < 4; q++) {
            __syncthreads();
            int nh = q >> 1;
            if (((ty >> 3) & 1) == (q & 1)) {
                int rl = (ty & 7) * 4;
#pragma unroll
                for (int i = 0; i < 4; i++) {
                    float s0, s1, s2, s3, s4, s5, s6, s7;
                    unpack2(acc[nh][i][0], s0, s1);
                    unpack2(acc[nh][i][1], s2, s3);
                    unpack2(acc[nh][i][2], s4, s5);
                    unpack2(acc[nh][i][3], s6, s7);
                    *(float4*)&sP[rl + i][tx * 4] = make_float4(
                        2.f * s0 - xxLo.x, 2.f * s1 - xxLo.y,
                        2.f * s2 - xxLo.z, 2.f * s3 - xxLo.w);
                    *(float4*)&sP[rl + i][64 + tx * 4] = make_float4(
                        2.f * s4 - xxHi.x, 2.f * s5 - xxHi.y,
                        2.f * s6 - xxHi.z, 2.f * s7 - xxHi.w);
                }
            }
            __syncthreads();

#pragma unroll
            for (int rr = 0; rr < 4; rr++) {
                int rl = w * 4 + rr;
                int gr = q * 32 + rl;
                float lv = -INFINITY; int li = 0;
                if (lane < TSEL) { lv = sVal[gr][lane]; li = sIdx[gr][lane]; }
                float thr = __shfl_sync(FULL, lv, TSEL - 1);
                float4 v = *(float4*)&sP[rl][lane * 4];
                float lmax = fmaxf(fmaxf(v.x, v.y), fmaxf(v.z, v.w));
                unsigned act = __ballot_sync(FULL, lmax > thr);
                while (act) {
                    int s = __ffs((int)act) - 1;
                    act &= act - 1;
                    float c0 = __shfl_sync(FULL, v.x, s);
                    float c1 = __shfl_sync(FULL, v.y, s);
                    float c2 = __shfl_sync(FULL, v.z, s);
                    float c3 = __shfl_sync(FULL, v.w, s);
                    int mb = m0 + s * 4;
                    float cs[4] = {c0, c1, c2, c3};
#pragma unroll
                    for (int i = 0; i < 4; i++) {
                        float cv = cs[i];
                        if (cv > thr) {
                            unsigned lt = __ballot_sync(FULL, lv < cv);
                            int pos = __ffs((int)lt) - 1;
                            float upv = __shfl_up_sync(FULL, lv, 1);
                            int   upi = __shfl_up_sync(FULL, li, 1);
                            if (lane > pos)       { lv = upv; li = upi; }
                            else if (lane == pos) { lv = cv;  li = mb + i; }
                            thr = __shfl_sync(FULL, lv, TSEL - 1);
                        }
                    }
                }
                if (lane < TSEL) { sVal[gr][lane] = lv; sIdx[gr][lane] = li; }
            }
        }
    }
    __syncthreads();

    int rowbase = (b << 11) + n0;
#pragma unroll
    for (int rr = 0; rr < 16; rr++) {
        int gr = w * 16 + rr;
        if (lane < TSEL) g_cand[(rowbase + gr) * TSEL + lane] = sIdx[gr][lane];
    }
}

// ---------------- K3: exact re-ranking via double-float (compensated fp32) ----------------
// TwoProd/TwoSum error-free transformations: effective precision ~2^-45, far
// beyond what's needed to reproduce the fp64 ranking — no fp64 instructions.
__device__ __forceinline__ void twosum(float a, float b, float& s, float& e) {
    s = a + b;
    float bb = s - a;
    e = (a - (s - bb)) + (b - bb);
}

__global__ __launch_bounds__(256) void refine_kernel(float* __restrict__ out, int write_idx) {
    __shared__ float sxn[8][Cn];
    const unsigned FULL = 0xffffffffu;
    int warp = threadIdx.x >> 5, lane = threadIdx.x & 31;
    int row = (blockIdx.x << 3) + warp;
    int b = row >> 11;

    const float* xn = g_xt + (size_t)row * Cn;
    sxn[warp][lane]      = xn[lane];
    sxn[warp][lane + 32] = xn[lane + 32];
    __syncwarp();

    float hi = -INFINITY, lo = 0.f;    // df score = 2*dot - xx
    int m = 0x7fffffff;
    if (lane < TSEL) {
        m = g_cand[row * TSEL + lane];
        const float4* xm4 = (const float4*)(g_xt + (size_t)((b << 11) + m) * Cn);
        float sh = 0.f, se = 0.f;      // running compensated sum of (2*a*v - v*v)
#pragma unroll
        for (int q = 0; q < 16; q++) {
            float4 v = xm4[q];
            float av[4] = {sxn[warp][q * 4], sxn[warp][q * 4 + 1],
                           sxn[warp][q * 4 + 2], sxn[warp][q * 4 + 3]};
            float vv[4] = {v.x, v.y, v.z, v.w};
#pragma unroll
            for (int i = 0; i < 4; i++) {
                float a = av[i], vm = vv[i];
                // term = 2*a*vm - vm*vm; exact products via FMA:
                float p1 = a * vm;                      // dot term
                float e1 = fmaf(a, vm, -p1);
                float p2 = vm * vm;                     // norm term
                float e2 = fmaf(vm, vm, -p2);
                float s1, t1; twosum(sh, 2.f * p1, s1, t1);
                se += t1 + 2.f * e1;
                float s2, t2; twosum(s1, -p2, s2, t2);
                se += t2 - e2;
                sh = s2;
            }
        }
        twosum(sh, se, hi, lo);        // renormalize
    }

    // stable O(TSEL^2) rank on (hi,lo) lexicographic; ties -> lower index
    int rank = 0;
#pragma unroll
    for (int i = 0; i < TSEL; i++) {
        float vhi = __shfl_sync(FULL, hi, i);
        float vlo = __shfl_sync(FULL, lo, i);
        int   mi  = __shfl_sync(FULL, m, i);
        bool gt = (vhi > hi) || (vhi == hi && (vlo > lo || (vlo == lo && mi < m)));
        if (i != lane && gt) rank++;
    }
    if (lane < TSEL && rank < Kn) {
        g_idx[row * Kn + rank] = m;
        if (write_idx) {
            const size_t FEAT = (size_t)Bn * 2 * Cn * Nn * Kn;
            out[FEAT + (size_t)row * Kn + rank] = (float)(m + b * Nn);
        }
    }
}

// ---------------- K4: branchless top-14-of-20 mean ----------------
__global__ __launch_bounds__(256) void smooth_kernel(const float* __restrict__ x) {
    int t = blockIdx.x * 256 + threadIdx.x;
    int n = t & (Nn - 1);
    int c = (t >> 11) & (Cn - 1);
    int b = t >> 17;
    const int* ip = g_idx + ((b << 11) + n) * Kn;
    const float* xr = x + ((size_t)(b * Cn + c) << 11);

    float s = 0.f;
    float bot[NBOT];
#pragma unroll
    for (int q = 0; q < NBOT; q++) bot[q] = INFINITY;

#pragma unroll
    for (int j = 0; j < Kn; j++) {
        float v = xr[ip[j]];
        s += v;
        float nv = v;
#pragma unroll
        for (int q = 0; q < NBOT; q++) {
            float lo = fminf(bot[q], nv);
            float hi = fmaxf(bot[q], nv);
            bot[q] = lo; nv = hi;
        }
    }
    float bs = bot[0] + bot[1] + bot[2] + bot[3] + bot[4] + bot[5];
    g_x1t[((size_t)(b * Cn + c) << 11) + n] = (s - bs) * (1.0f / 14.0f);
}

// ---------------- K5: feature (B, 2C, N, K) ----------------
__global__ __launch_bounds__(256) void feature_kernel(const float* __restrict__ x,
                                                      float* __restrict__ out) {
    unsigned f = blockIdx.x * 256u + threadIdx.x;
    unsigned j = f % 20u;
    unsigned r = f / 20u;
    unsigned n = r & (Nn - 1);
    unsigned r2 = r >> 11;
    unsigned ch = r2 & 127u;
    unsigned b = r2 >> 7;

    float val;
    if (ch >= (unsigned)Cn) {
        val = x[((size_t)(b * Cn + (ch - Cn)) << 11) + n];
    } else {
        int m = g_idx[((b << 11) + n) * Kn + j];
        size_t rowo = (size_t)(b * Cn + ch) << 11;
        val = g_x1t[rowo + m] - x[rowo + n];
    }
    out[f] = val;
}

// ---------------- launch ----------------
extern "C" void kernel_launch(void* const* d_in, const int* in_sizes, int n_in,
                              void* d_out, int out_size) {
    const float* x = nullptr;
    for (int i = 0; i < n_in; i++) {
        if (in_sizes[i] == Bn * Cn * Nn) { x = (const float*)d_in[i]; break; }
    }
    float* out = (float*)d_out;

    const long long FEAT = (long long)Bn * 2 * Cn * Nn * Kn;          // 83886080
    const long long IDXE = (long long)Bn * Nn * Kn;                   // 655360
    int write_idx = ((long long)out_size >= FEAT + IDXE) ? 1 : 0;

    cudaFuncSetAttribute(knn_kernel, cudaFuncAttributeMaxDynamicSharedMemorySize, SM_TOTAL);

    dim3 gt(Nn / 32, Cn / 32, Bn);
    xt_kernel<<<gt, 256>>>(x);

    xx_kernel<<<(Bn * Nn + 255) / 256, 256>>>(x);

    dim3 gk(Nn / 128, Bn);                                            // (16, 16)
    knn_kernel<<<gk, 256, SM_TOTAL>>>(x);

    refine_kernel<<<Bn * Nn / 8, 256>>>(out, write_idx);

    smooth_kernel<<<Bn * Cn * Nn / 256, 256>>>(x);

    feature_kernel<<<(unsigned)(FEAT / 256), 256>>>(x, out);
}

// round 7
// speedup vs baseline: 1.9103x; 1.0416x over previous
#include <cuda_runtime.h>
#include <cuda_bf16.h>
#include <cstdint>
#include <cstddef>

#define Bn 16
#define Cn 64
#define Nn 2048
#define Kn 20
#define NBOT 6    // K - ceil(2K/3)
#define TSEL 22   // preselected candidates per row

// ---- scratch (static device memory; no allocations allowed) ----
static __device__ float g_xx[Bn * Nn];                   // squared norms
static __device__ float g_xt[(size_t)Bn * Nn * Cn];      // transposed x, (B,N,C)
static __device__ int   g_cand[Bn * Nn * TSEL];          // fp32 top-22 candidates
static __device__ int   g_idx[Bn * Nn * Kn];             // exact top-K neighbor indices
static __device__ float g_x1t[(size_t)Bn * Cn * Nn];     // smoothed features, (B,C,N)

// ---------------- packed f32x2 helpers ----------------
__device__ __forceinline__ unsigned long long pack2(float lo, float hi) {
    unsigned long long r;
    asm("mov.b64 %0, {%1, %2};" : "=l"(r) : "f"(lo), "f"(hi));
    return r;
}
__device__ __forceinline__ void unpack2(unsigned long long v, float& lo, float& hi) {
    asm("mov.b64 {%0, %1}, %2;" : "=f"(lo), "=f"(hi) : "l"(v));
}
__device__ __forceinline__ unsigned long long fma2(unsigned long long a,
                                                   unsigned long long b,
                                                   unsigned long long c) {
    unsigned long long d;
    asm("fma.rn.f32x2 %0, %1, %2, %3;" : "=l"(d) : "l"(a), "l"(b), "l"(c));
    return d;
}

// ---------------- K0: transpose x (B,C,N) -> g_xt (B,N,C) ----------------
__global__ __launch_bounds__(256) void xt_kernel(const float* __restrict__ x) {
    __shared__ float tile[32][33];
    int b = blockIdx.z, c0 = blockIdx.y * 32, n0 = blockIdx.x * 32;
    int tx = threadIdx.x & 31, ty = threadIdx.x >> 5;
#pragma unroll
    for (int i = ty; i < 32; i += 8)
        tile[i][tx] = x[((size_t)(b * Cn + c0 + i) << 11) + n0 + tx];
    __syncthreads();
#pragma unroll
    for (int i = ty; i < 32; i += 8)
        g_xt[(size_t)((b << 11) + n0 + i) * Cn + c0 + tx] = tile[tx][i];
}

// ---------------- K1: squared norms ----------------
__global__ void xx_kernel(const float* __restrict__ x) {
    int t = blockIdx.x * blockDim.x + threadIdx.x;
    if (t >= Bn * Nn) return;
    int b = t >> 11, n = t & (Nn - 1);
    const float* xp = x + (size_t)b * Cn * Nn + n;
    float s = 0.f;
#pragma unroll
    for (int c = 0; c < Cn; c++) {
        float v = xp[(size_t)c * Nn];
        s = fmaf(v, v, s);
    }
    g_xx[t] = s;
}

// ---------------- K2: fused pd-GEMM + in-register top-22 preselect ----------------
// smem: sA 32KB | sB 32KB | sXX 512B | sVal 11.25KB | sIdx 11.25KB = 88576 B
#define SM_TOTAL 88576

// warp-cooperative insertion scan over one ballot mask of 4-col groups
#define PROCESS(ACT, BASE, V0, V1, V2, V3)                              \
    while (ACT) {                                                       \
        int s_ = __ffs((int)(ACT)) - 1; (ACT) &= (ACT) - 1;             \
        float c0_ = __shfl_sync(FULL, V0, s_);                          \
        float c1_ = __shfl_sync(FULL, V1, s_);                          \
        float c2_ = __shfl_sync(FULL, V2, s_);                          \
        float c3_ = __shfl_sync(FULL, V3, s_);                          \
        int mb_ = (BASE) + (s_ & 15) * 4;                               \
        float cs_[4] = {c0_, c1_, c2_, c3_};                            \
        _Pragma("unroll")                                               \
        for (int i_ = 0; i_ < 4; i_++) {                                \
            float cv_ = cs_[i_];                                        \
            if (cv_ > thr) {                                            \
                unsigned lt_ = __ballot_sync(FULL, lv < cv_);           \
                int pos_ = __ffs((int)lt_) - 1;                         \
                float upv_ = __shfl_up_sync(FULL, lv, 1);               \
                int   upi_ = __shfl_up_sync(FULL, li, 1);               \
                if (lane > pos_)       { lv = upv_; li = upi_; }        \
                else if (lane == pos_) { lv = cv_;  li = mb_ + i_; }    \
                thr = __shfl_sync(FULL, lv, TSEL - 1);                  \
            }                                                           \
        }                                                               \
    }

__global__ __launch_bounds__(256, 2) void knn_kernel(const float* __restrict__ x) {
    extern __shared__ char sm[];
    float (*sA)[128]    = (float(*)[128])(sm);
    float (*sB)[128]    = (float(*)[128])(sm + 32768);
    float* sXX          = (float*)(sm + 65536);
    float (*sVal)[TSEL] = (float(*)[TSEL])(sm + 66048);
    int   (*sIdx)[TSEL] = (int(*)[TSEL])(sm + 77312);

    const unsigned FULL = 0xffffffffu;
    int t    = threadIdx.x;
    int lane = t & 31;
    int w    = t >> 5;
    int tx   = t & 15;           // m micro-group
    int ty   = t >> 4;           // n micro-group (warp w owns ty = 2w, 2w+1)
    int b    = blockIdx.y;
    int n0   = blockIdx.x * 128;
    const float* xb = x + (size_t)b * Cn * Nn;

    for (int i = t; i < 128 * TSEL; i += 256) {
        ((float*)sVal)[i] = -INFINITY;
        ((int*)sIdx)[i]   = 0;
    }
    // load A tile scaled by 2 (exact power-of-2: scores bit-identical to 2*dot)
#pragma unroll
    for (int p = 0; p < 8; p++) {
        int lin = t + p * 256;
        int c = lin >> 5, i4 = lin & 31;
        float4 v = *(const float4*)(xb + (size_t)c * Nn + n0 + i4 * 4);
        v.x *= 2.f; v.y *= 2.f; v.z *= 2.f; v.w *= 2.f;
        *(float4*)&sA[c][i4 * 4] = v;
    }

    for (int mt = 0; mt < 16; mt++) {
        int m0 = mt * 128;
        __syncthreads();   // all warps done with previous tile's compute
#pragma unroll
        for (int p = 0; p < 8; p++) {
            int lin = t + p * 256;
            int c = lin >> 5, i4 = lin & 31;
            *(float4*)&sB[c][i4 * 4] = *(const float4*)(xb + (size_t)c * Nn + m0 + i4 * 4);
        }
        if (t < 32) *(float4*)&sXX[t * 4] = *(const float4*)(g_xx + b * Nn + m0 + t * 4);
        __syncthreads();

        unsigned long long acc[2][4][4];
#pragma unroll
        for (int h = 0; h < 2; h++)
#pragma unroll
            for (int i = 0; i < 4; i++)
#pragma unroll
                for (int p = 0; p < 4; p++) acc[h][i][p] = 0ull;

#pragma unroll 8
        for (int c = 0; c < Cn; c++) {
            float4 aLo = *(float4*)&sA[c][ty * 4];
            float4 aHi = *(float4*)&sA[c][64 + ty * 4];
            ulonglong2 b0 = *(ulonglong2*)&sB[c][tx * 4];
            ulonglong2 b1 = *(ulonglong2*)&sB[c][64 + tx * 4];
            const float* al = &aLo.x;
            const float* ah = &aHi.x;
#pragma unroll
            for (int i = 0; i < 4; i++) {
                unsigned long long a0 = pack2(al[i], al[i]);
                acc[0][i][0] = fma2(b0.x, a0, acc[0][i][0]);
                acc[0][i][1] = fma2(b0.y, a0, acc[0][i][1]);
                acc[0][i][2] = fma2(b1.x, a0, acc[0][i][2]);
                acc[0][i][3] = fma2(b1.y, a0, acc[0][i][3]);
                unsigned long long a1 = pack2(ah[i], ah[i]);
                acc[1][i][0] = fma2(b0.x, a1, acc[1][i][0]);
                acc[1][i][1] = fma2(b0.y, a1, acc[1][i][1]);
                acc[1][i][2] = fma2(b1.x, a1, acc[1][i][2]);
                acc[1][i][3] = fma2(b1.y, a1, acc[1][i][3]);
            }
        }

        float4 xxLo = *(float4*)&sXX[tx * 4];
        float4 xxHi = *(float4*)&sXX[64 + tx * 4];

        // ---- in-register filter: warp w owns rows 8w..8w+7 (+64) ----
#pragma unroll
        for (int h = 0; h < 2; h++) {
#pragma unroll
            for (int i = 0; i < 4; i++) {
                float s0, s1, s2, s3, s4, s5, s6, s7;
                unpack2(acc[h][i][0], s0, s1);
                unpack2(acc[h][i][1], s2, s3);
                unpack2(acc[h][i][2], s4, s5);
                unpack2(acc[h][i][3], s6, s7);
                s0 -= xxLo.x; s1 -= xxLo.y; s2 -= xxLo.z; s3 -= xxLo.w;
                s4 -= xxHi.x; s5 -= xxHi.y; s6 -= xxHi.z; s7 -= xxHi.w;
                float lmLo = fmaxf(fmaxf(s0, s1), fmaxf(s2, s3));
                float lmHi = fmaxf(fmaxf(s4, s5), fmaxf(s6, s7));
#pragma unroll
                for (int half = 0; half < 2; half++) {
                    // row held by lanes [half*16, half*16+16)
                    int gr = 64 * h + 8 * w + 4 * half + i;
                    unsigned hm = half ? 0xFFFF0000u : 0x0000FFFFu;
                    float lv = -INFINITY; int li = 0;
                    if (lane < TSEL) { lv = sVal[gr][lane]; li = sIdx[gr][lane]; }
                    float thr = __shfl_sync(FULL, lv, TSEL - 1);
                    unsigned act = __ballot_sync(FULL, lmLo > thr) & hm;
                    PROCESS(act, m0, s0, s1, s2, s3)
                    act = __ballot_sync(FULL, lmHi > thr) & hm;
                    PROCESS(act, m0 + 64, s4, s5, s6, s7)
                    if (lane < TSEL) { sVal[gr][lane] = lv; sIdx[gr][lane] = li; }
                }
            }
        }
    }
    __syncthreads();

    int rowbase = (b << 11) + n0;
#pragma unroll
    for (int rr = 0; rr < 16; rr++) {
        int gr = w * 16 + rr;
        if (lane < TSEL) g_cand[(rowbase + gr) * TSEL + lane] = sIdx[gr][lane];
    }
}

// ---------------- K3: exact re-ranking via double-float (compensated fp32) ----------------
__device__ __forceinline__ void twosum(float a, float b, float& s, float& e) {
    s = a + b;
    float bb = s - a;
    e = (a - (s - bb)) + (b - bb);
}

__global__ __launch_bounds__(256) void refine_kernel(float* __restrict__ out, int write_idx) {
    __shared__ float sxn[8][Cn];
    const unsigned FULL = 0xffffffffu;
    int warp = threadIdx.x >> 5, lane = threadIdx.x & 31;
    int row = (blockIdx.x << 3) + warp;
    int b = row >> 11;

    const float* xn = g_xt + (size_t)row * Cn;
    sxn[warp][lane]      = xn[lane];
    sxn[warp][lane + 32] = xn[lane + 32];
    __syncwarp();

    float hi = -INFINITY, lo = 0.f;    // df score = 2*dot - xx
    int m = 0x7fffffff;
    if (lane < TSEL) {
        m = g_cand[row * TSEL + lane];
        const float4* xm4 = (const float4*)(g_xt + (size_t)((b << 11) + m) * Cn);
        float sh = 0.f, se = 0.f;
#pragma unroll
        for (int q = 0; q < 16; q++) {
            float4 v = xm4[q];
            float av[4] = {sxn[warp][q * 4], sxn[warp][q * 4 + 1],
                           sxn[warp][q * 4 + 2], sxn[warp][q * 4 + 3]};
            float vv[4] = {v.x, v.y, v.z, v.w};
#pragma unroll
            for (int i = 0; i < 4; i++) {
                float a = av[i], vm = vv[i];
                float p1 = a * vm;
                float e1 = fmaf(a, vm, -p1);
                float p2 = vm * vm;
                float e2 = fmaf(vm, vm, -p2);
                float s1, t1; twosum(sh, 2.f * p1, s1, t1);
                se += t1 + 2.f * e1;
                float s2, t2; twosum(s1, -p2, s2, t2);
                se += t2 - e2;
                sh = s2;
            }
        }
        twosum(sh, se, hi, lo);
    }

    int rank = 0;
#pragma unroll
    for (int i = 0; i < TSEL; i++) {
        float vhi = __shfl_sync(FULL, hi, i);
        float vlo = __shfl_sync(FULL, lo, i);
        int   mi  = __shfl_sync(FULL, m, i);
        bool gt = (vhi > hi) || (vhi == hi && (vlo > lo || (vlo == lo && mi < m)));
        if (i != lane && gt) rank++;
    }
    if (lane < TSEL && rank < Kn) {
        g_idx[row * Kn + rank] = m;
        if (write_idx) {
            const size_t FEAT = (size_t)Bn * 2 * Cn * Nn * Kn;
            out[FEAT + (size_t)row * Kn + rank] = (float)(m + b * Nn);
        }
    }
}

// ---------------- K4: branchless top-14-of-20 mean ----------------
__global__ __launch_bounds__(256) void smooth_kernel(const float* __restrict__ x) {
    int t = blockIdx.x * 256 + threadIdx.x;
    int n = t & (Nn - 1);
    int c = (t >> 11) & (Cn - 1);
    int b = t >> 17;
    const int* ip = g_idx + ((b << 11) + n) * Kn;
    const float* xr = x + ((size_t)(b * Cn + c) << 11);

    float s = 0.f;
    float bot[NBOT];
#pragma unroll
    for (int q = 0; q < NBOT; q++) bot[q] = INFINITY;

#pragma unroll
    for (int j = 0; j < Kn; j++) {
        float v = xr[ip[j]];
        s += v;
        float nv = v;
#pragma unroll
        for (int q = 0; q < NBOT; q++) {
            float lo = fminf(bot[q], nv);
            float hi = fmaxf(bot[q], nv);
            bot[q] = lo; nv = hi;
        }
    }
    float bs = bot[0] + bot[1] + bot[2] + bot[3] + bot[4] + bot[5];
    g_x1t[((size_t)(b * Cn + c) << 11) + n] = (s - bs) * (1.0f / 14.0f);
}

// ---------------- K5: feature (B, 2C, N, K) ----------------
__global__ __launch_bounds__(256) void feature_kernel(const float* __restrict__ x,
                                                      float* __restrict__ out) {
    unsigned f = blockIdx.x * 256u + threadIdx.x;
    unsigned j = f % 20u;
    unsigned r = f / 20u;
    unsigned n = r & (Nn - 1);
    unsigned r2 = r >> 11;
    unsigned ch = r2 & 127u;
    unsigned b = r2 >> 7;

    float val;
    if (ch >= (unsigned)Cn) {
        val = x[((size_t)(b * Cn + (ch - Cn)) << 11) + n];
    } else {
        int m = g_idx[((b << 11) + n) * Kn + j];
        size_t rowo = (size_t)(b * Cn + ch) << 11;
        val = g_x1t[rowo + m] - x[rowo + n];
    }
    out[f] = val;
}

// ---------------- launch ----------------
extern "C" void kernel_launch(void* const* d_in, const int* in_sizes, int n_in,
                              void* d_out, int out_size) {
    const float* x = nullptr;
    for (int i = 0; i < n_in; i++) {
        if (in_sizes[i] == Bn * Cn * Nn) { x = (const float*)d_in[i]; break; }
    }
    float* out = (float*)d_out;

    const long long FEAT = (long long)Bn * 2 * Cn * Nn * Kn;          // 83886080
    const long long IDXE = (long long)Bn * Nn * Kn;                   // 655360
    int write_idx = ((long long)out_size >= FEAT + IDXE) ? 1 : 0;

    cudaFuncSetAttribute(knn_kernel, cudaFuncAttributeMaxDynamicSharedMemorySize, SM_TOTAL);

    dim3 gt(Nn / 32, Cn / 32, Bn);
    xt_kernel<<<gt, 256>>>(x);

    xx_kernel<<<(Bn * Nn + 255) / 256, 256>>>(x);

    dim3 gk(Nn / 128, Bn);                                            // (16, 16)
    knn_kernel<<<gk, 256, SM_TOTAL>>>(x);

    refine_kernel<<<Bn * Nn / 8, 256>>>(out, write_idx);

    smooth_kernel<<<Bn * Cn * Nn / 256, 256>>>(x);

    feature_kernel<<<(unsigned)(FEAT / 256), 256>>>(x, out);
}

// round 8
// speedup vs baseline: 2.5060x; 1.3118x over previous
#include <cuda_runtime.h>
#include <cuda_bf16.h>
#include <cstdint>
#include <cstddef>

#define Bn 16
#define Cn 64
#define Nn 2048
#define Kn 20
#define NBOT 6    // K - ceil(2K/3)
#define TSEL 22   // preselected candidates per row

// ---- scratch (static device memory; no allocations allowed) ----
static __device__ float g_xx[Bn * Nn];                   // squared norms
static __device__ float g_xt[(size_t)Bn * Nn * Cn];      // transposed x, (B,N,C)
static __device__ int   g_cand[Bn * Nn * TSEL];          // fp32 top-22 candidates
static __device__ int   g_idx[Bn * Nn * Kn];             // exact top-K neighbor indices
static __device__ float g_x1n[(size_t)Bn * Nn * Cn];     // smoothed features, (B,N,C)

// ---------------- packed f32x2 helpers ----------------
__device__ __forceinline__ unsigned long long pack2(float lo, float hi) {
    unsigned long long r;
    asm("mov.b64 %0, {%1, %2};" : "=l"(r) : "f"(lo), "f"(hi));
    return r;
}
__device__ __forceinline__ void unpack2(unsigned long long v, float& lo, float& hi) {
    asm("mov.b64 {%0, %1}, %2;" : "=f"(lo), "=f"(hi) : "l"(v));
}
__device__ __forceinline__ unsigned long long fma2(unsigned long long a,
                                                   unsigned long long b,
                                                   unsigned long long c) {
    unsigned long long d;
    asm("fma.rn.f32x2 %0, %1, %2, %3;" : "=l"(d) : "l"(a), "l"(b), "l"(c));
    return d;
}

// ---------------- K0: transpose x (B,C,N) -> g_xt (B,N,C) ----------------
__global__ __launch_bounds__(256) void xt_kernel(const float* __restrict__ x) {
    __shared__ float tile[32][33];
    int b = blockIdx.z, c0 = blockIdx.y * 32, n0 = blockIdx.x * 32;
    int tx = threadIdx.x & 31, ty = threadIdx.x >> 5;
#pragma unroll
    for (int i = ty; i < 32; i += 8)
        tile[i][tx] = x[((size_t)(b * Cn + c0 + i) << 11) + n0 + tx];
    __syncthreads();
#pragma unroll
    for (int i = ty; i < 32; i += 8)
        g_xt[(size_t)((b << 11) + n0 + i) * Cn + c0 + tx] = tile[tx][i];
}

// ---------------- K1: squared norms ----------------
__global__ void xx_kernel(const float* __restrict__ x) {
    int t = blockIdx.x * blockDim.x + threadIdx.x;
    if (t >= Bn * Nn) return;
    int b = t >> 11, n = t & (Nn - 1);
    const float* xp = x + (size_t)b * Cn * Nn + n;
    float s = 0.f;
#pragma unroll
    for (int c = 0; c < Cn; c++) {
        float v = xp[(size_t)c * Nn];
        s = fmaf(v, v, s);
    }
    g_xx[t] = s;
}

// ---------------- K2: fused pd-GEMM + in-register top-22 preselect ----------------
// smem: sA 32KB | sB 32KB | sXX 512B | sVal 11.25KB | sIdx 11.25KB = 88576 B
#define SM_TOTAL 88576

#define PROCESS(ACT, BASE, V0, V1, V2, V3)                              \
    while (ACT) {                                                       \
        int s_ = __ffs((int)(ACT)) - 1; (ACT) &= (ACT) - 1;             \
        float c0_ = __shfl_sync(FULL, V0, s_);                          \
        float c1_ = __shfl_sync(FULL, V1, s_);                          \
        float c2_ = __shfl_sync(FULL, V2, s_);                          \
        float c3_ = __shfl_sync(FULL, V3, s_);                          \
        int mb_ = (BASE) + (s_ & 15) * 4;                               \
        float cs_[4] = {c0_, c1_, c2_, c3_};                            \
        _Pragma("unroll")                                               \
        for (int i_ = 0; i_ < 4; i_++) {                                \
            float cv_ = cs_[i_];                                        \
            if (cv_ > thr) {                                            \
                unsigned lt_ = __ballot_sync(FULL, lv < cv_);           \
                int pos_ = __ffs((int)lt_) - 1;                         \
                float upv_ = __shfl_up_sync(FULL, lv, 1);               \
                int   upi_ = __shfl_up_sync(FULL, li, 1);               \
                if (lane > pos_)       { lv = upv_; li = upi_; }        \
                else if (lane == pos_) { lv = cv_;  li = mb_ + i_; }    \
                thr = __shfl_sync(FULL, lv, TSEL - 1);                  \
            }                                                           \
        }                                                               \
    }

__global__ __launch_bounds__(256, 2) void knn_kernel(const float* __restrict__ x) {
    extern __shared__ char sm[];
    float (*sA)[128]    = (float(*)[128])(sm);
    float (*sB)[128]    = (float(*)[128])(sm + 32768);
    float* sXX          = (float*)(sm + 65536);
    float (*sVal)[TSEL] = (float(*)[TSEL])(sm + 66048);
    int   (*sIdx)[TSEL] = (int(*)[TSEL])(sm + 77312);

    const unsigned FULL = 0xffffffffu;
    int t    = threadIdx.x;
    int lane = t & 31;
    int w    = t >> 5;
    int tx   = t & 15;
    int ty   = t >> 4;
    int b    = blockIdx.y;
    int n0   = blockIdx.x * 128;
    const float* xb = x + (size_t)b * Cn * Nn;

    for (int i = t; i < 128 * TSEL; i += 256) {
        ((float*)sVal)[i] = -INFINITY;
        ((int*)sIdx)[i]   = 0;
    }
#pragma unroll
    for (int p = 0; p < 8; p++) {
        int lin = t + p * 256;
        int c = lin >> 5, i4 = lin & 31;
        float4 v = *(const float4*)(xb + (size_t)c * Nn + n0 + i4 * 4);
        v.x *= 2.f; v.y *= 2.f; v.z *= 2.f; v.w *= 2.f;
        *(float4*)&sA[c][i4 * 4] = v;
    }

    for (int mt = 0; mt < 16; mt++) {
        int m0 = mt * 128;
        __syncthreads();
#pragma unroll
        for (int p = 0; p < 8; p++) {
            int lin = t + p * 256;
            int c = lin >> 5, i4 = lin & 31;
            *(float4*)&sB[c][i4 * 4] = *(const float4*)(xb + (size_t)c * Nn + m0 + i4 * 4);
        }
        if (t < 32) *(float4*)&sXX[t * 4] = *(const float4*)(g_xx + b * Nn + m0 + t * 4);
        __syncthreads();

        unsigned long long acc[2][4][4];
#pragma unroll
        for (int h = 0; h < 2; h++)
#pragma unroll
            for (int i = 0; i < 4; i++)
#pragma unroll
                for (int p = 0; p < 4; p++) acc[h][i][p] = 0ull;

#pragma unroll 8
        for (int c = 0; c < Cn; c++) {
            float4 aLo = *(float4*)&sA[c][ty * 4];
            float4 aHi = *(float4*)&sA[c][64 + ty * 4];
            ulonglong2 b0 = *(ulonglong2*)&sB[c][tx * 4];
            ulonglong2 b1 = *(ulonglong2*)&sB[c][64 + tx * 4];
            const float* al = &aLo.x;
            const float* ah = &aHi.x;
#pragma unroll
            for (int i = 0; i < 4; i++) {
                unsigned long long a0 = pack2(al[i], al[i]);
                acc[0][i][0] = fma2(b0.x, a0, acc[0][i][0]);
                acc[0][i][1] = fma2(b0.y, a0, acc[0][i][1]);
                acc[0][i][2] = fma2(b1.x, a0, acc[0][i][2]);
                acc[0][i][3] = fma2(b1.y, a0, acc[0][i][3]);
                unsigned long long a1 = pack2(ah[i], ah[i]);
                acc[1][i][0] = fma2(b0.x, a1, acc[1][i][0]);
                acc[1][i][1] = fma2(b0.y, a1, acc[1][i][1]);
                acc[1][i][2] = fma2(b1.x, a1, acc[1][i][2]);
                acc[1][i][3] = fma2(b1.y, a1, acc[1][i][3]);
            }
        }

        float4 xxLo = *(float4*)&sXX[tx * 4];
        float4 xxHi = *(float4*)&sXX[64 + tx * 4];

#pragma unroll
        for (int h = 0; h < 2; h++) {
#pragma unroll
            for (int i = 0; i < 4; i++) {
                float s0, s1, s2, s3, s4, s5, s6, s7;
                unpack2(acc[h][i][0], s0, s1);
                unpack2(acc[h][i][1], s2, s3);
                unpack2(acc[h][i][2], s4, s5);
                unpack2(acc[h][i][3], s6, s7);
                s0 -= xxLo.x; s1 -= xxLo.y; s2 -= xxLo.z; s3 -= xxLo.w;
                s4 -= xxHi.x; s5 -= xxHi.y; s6 -= xxHi.z; s7 -= xxHi.w;
                float lmLo = fmaxf(fmaxf(s0, s1), fmaxf(s2, s3));
                float lmHi = fmaxf(fmaxf(s4, s5), fmaxf(s6, s7));
#pragma unroll
                for (int half = 0; half < 2; half++) {
                    int gr = 64 * h + 8 * w + 4 * half + i;
                    unsigned hm = half ? 0xFFFF0000u : 0x0000FFFFu;
                    float lv = -INFINITY; int li = 0;
                    if (lane < TSEL) { lv = sVal[gr][lane]; li = sIdx[gr][lane]; }
                    float thr = __shfl_sync(FULL, lv, TSEL - 1);
                    unsigned act = __ballot_sync(FULL, lmLo > thr) & hm;
                    PROCESS(act, m0, s0, s1, s2, s3)
                    act = __ballot_sync(FULL, lmHi > thr) & hm;
                    PROCESS(act, m0 + 64, s4, s5, s6, s7)
                    if (lane < TSEL) { sVal[gr][lane] = lv; sIdx[gr][lane] = li; }
                }
            }
        }
    }
    __syncthreads();

    int rowbase = (b << 11) + n0;
#pragma unroll
    for (int rr = 0; rr < 16; rr++) {
        int gr = w * 16 + rr;
        if (lane < TSEL) g_cand[(rowbase + gr) * TSEL + lane] = sIdx[gr][lane];
    }
}

// ---------------- K3: exact re-ranking via double-float (compensated fp32) ----------------
__device__ __forceinline__ void twosum(float a, float b, float& s, float& e) {
    s = a + b;
    float bb = s - a;
    e = (a - (s - bb)) + (b - bb);
}

__global__ __launch_bounds__(256) void refine_kernel(float* __restrict__ out, int write_idx) {
    __shared__ float sxn[8][Cn];
    const unsigned FULL = 0xffffffffu;
    int warp = threadIdx.x >> 5, lane = threadIdx.x & 31;
    int row = (blockIdx.x << 3) + warp;
    int b = row >> 11;

    const float* xn = g_xt + (size_t)row * Cn;
    sxn[warp][lane]      = xn[lane];
    sxn[warp][lane + 32] = xn[lane + 32];
    __syncwarp();

    float hi = -INFINITY, lo = 0.f;
    int m = 0x7fffffff;
    if (lane < TSEL) {
        m = g_cand[row * TSEL + lane];
        const float4* xm4 = (const float4*)(g_xt + (size_t)((b << 11) + m) * Cn);
        float sh = 0.f, se = 0.f;
#pragma unroll
        for (int q = 0; q < 16; q++) {
            float4 v = xm4[q];
            float av[4] = {sxn[warp][q * 4], sxn[warp][q * 4 + 1],
                           sxn[warp][q * 4 + 2], sxn[warp][q * 4 + 3]};
            float vv[4] = {v.x, v.y, v.z, v.w};
#pragma unroll
            for (int i = 0; i < 4; i++) {
                float a = av[i], vm = vv[i];
                float p1 = a * vm;
                float e1 = fmaf(a, vm, -p1);
                float p2 = vm * vm;
                float e2 = fmaf(vm, vm, -p2);
                float s1, t1; twosum(sh, 2.f * p1, s1, t1);
                se += t1 + 2.f * e1;
                float s2, t2; twosum(s1, -p2, s2, t2);
                se += t2 - e2;
                sh = s2;
            }
        }
        twosum(sh, se, hi, lo);
    }

    int rank = 0;
#pragma unroll
    for (int i = 0; i < TSEL; i++) {
        float vhi = __shfl_sync(FULL, hi, i);
        float vlo = __shfl_sync(FULL, lo, i);
        int   mi  = __shfl_sync(FULL, m, i);
        bool gt = (vhi > hi) || (vhi == hi && (vlo > lo || (vlo == lo && mi < m)));
        if (i != lane && gt) rank++;
    }
    if (lane < TSEL && rank < Kn) {
        g_idx[row * Kn + rank] = m;
        if (write_idx) {
            const size_t FEAT = (size_t)Bn * 2 * Cn * Nn * Kn;
            out[FEAT + (size_t)row * Kn + rank] = (float)(m + b * Nn);
        }
    }
}

// ---------------- K4: top-14-of-20 mean, (n,c)-mapped, writes (B,N,C) ----------------
__global__ __launch_bounds__(256) void smooth_kernel() {
    int t = threadIdx.x;
    int c = t & 63, nl = t >> 6;                 // 4 rows per block
    int bn = blockIdx.x * 4 + nl;                // global b*N + n
    int b = bn >> 11;
    const int* ip = g_idx + bn * Kn;
    const float* xtb = g_xt + ((size_t)b << 11) * Cn;

    float s = 0.f;
    float bot[NBOT];
#pragma unroll
    for (int q = 0; q < NBOT; q++) bot[q] = INFINITY;

#pragma unroll
    for (int j = 0; j < Kn; j++) {
        int m = ip[j];                            // broadcast across 64 threads
        float v = xtb[(size_t)m * Cn + c];        // coalesced 128B per warp
        s += v;
        float nv = v;
#pragma unroll
        for (int q = 0; q < NBOT; q++) {
            float lo = fminf(bot[q], nv);
            float hi = fmaxf(bot[q], nv);
            bot[q] = lo; nv = hi;
        }
    }
    float bs = bot[0] + bot[1] + bot[2] + bot[3] + bot[4] + bot[5];
    g_x1n[(size_t)bn * Cn + c] = (s - bs) * (1.0f / 14.0f);
}

// ---------------- K5: feature (B, 2C, N, K), smem-staged row gathers ----------------
#define FPAD 161
__global__ __launch_bounds__(256) void feature_kernel(float* __restrict__ out) {
    __shared__ float sf[Cn][FPAD];    // sf[c][p], p = n*20+j  (41.2 KB)
    __shared__ float sxe[Cn][9];      // x[b][c][n0+n]
    __shared__ int   smi[160];
    int t = threadIdx.x, lane = t & 31, w = t >> 5;
    int b  = blockIdx.x >> 8;         // 256 n-groups per batch
    int n0 = (blockIdx.x & 255) * 8;
    int rowbase = (b << 11) + n0;

    if (t < 160) smi[t] = g_idx[rowbase * Kn + t];
    {
        int c = t & 63, n = t >> 6;   // n in 0..3, plus n+4
        sxe[c][n]     = g_xt[(size_t)(rowbase + n) * Cn + c];
        sxe[c][n + 4] = g_xt[(size_t)(rowbase + n + 4) * Cn + c];
    }
    __syncthreads();

    // stage 160 x1 rows (contiguous 256B each), warp w owns p = 20w..20w+19
#pragma unroll 5
    for (int q = 0; q < 20; q++) {
        int p = w * 20 + q;
        const float* r = g_x1n + (size_t)((b << 11) + smi[p]) * Cn;
        sf[lane][p]      = r[lane];
        sf[lane + 32][p] = r[lane + 32];
    }
    __syncthreads();

    // write: warp w owns channels 16w..16w+15; 160 consecutive floats per ch
#pragma unroll
    for (int q = 0; q < 16; q++) {
        int ch = w * 16 + q;
        size_t base = ((size_t)(b * 128 + ch) * Nn + n0) * Kn;
        if (ch < Cn) {
#pragma unroll
            for (int r5 = 0; r5 < 5; r5++) {
                int p = lane + 32 * r5;
                int n = p / 20;
                out[base + p] = sf[ch][p] - sxe[ch][n];
            }
        } else {
#pragma unroll
            for (int r5 = 0; r5 < 5; r5++) {
                int p = lane + 32 * r5;
                int n = p / 20;
                out[base + p] = sxe[ch - Cn][n];
            }
        }
    }
}

// ---------------- launch ----------------
extern "C" void kernel_launch(void* const* d_in, const int* in_sizes, int n_in,
                              void* d_out, int out_size) {
    const float* x = nullptr;
    for (int i = 0; i < n_in; i++) {
        if (in_sizes[i] == Bn * Cn * Nn) { x = (const float*)d_in[i]; break; }
    }
    float* out = (float*)d_out;

    const long long FEAT = (long long)Bn * 2 * Cn * Nn * Kn;          // 83886080
    const long long IDXE = (long long)Bn * Nn * Kn;                   // 655360
    int write_idx = ((long long)out_size >= FEAT + IDXE) ? 1 : 0;

    cudaFuncSetAttribute(knn_kernel, cudaFuncAttributeMaxDynamicSharedMemorySize, SM_TOTAL);

    dim3 gt(Nn / 32, Cn / 32, Bn);
    xt_kernel<<<gt, 256>>>(x);

    xx_kernel<<<(Bn * Nn + 255) / 256, 256>>>(x);

    dim3 gk(Nn / 128, Bn);                                            // (16, 16)
    knn_kernel<<<gk, 256, SM_TOTAL>>>(x);

    refine_kernel<<<Bn * Nn / 8, 256>>>(out, write_idx);

    smooth_kernel<<<Bn * Nn / 4, 256>>>();                            // 8192 blocks

    feature_kernel<<<Bn * (Nn / 8), 256>>>(out);                      // 4096 blocks
}